// round 16
// baseline (speedup 1.0000x reference)
#include <cuda_runtime.h>
#include <cuda_fp16.h>
#include <cstdint>
#include <math.h>

#define HID 128
#define SDF_THRESH 5e-05f
#define ROWB 272              // padded row stride (bytes) for fp16[128] rows

// shared-memory byte offsets (per-CTA dynamic, all 16B aligned)
#define SW_HI  0              // W2' hi: 128 rows x 272B = 34816  (W2'[m][k] = W2[k][m])
#define SW_LO  34816          // W2' lo: 34816
#define W2IMG_BYTES 69632     // hi+lo image, copied verbatim from gmem
#define OFF_PK 69632          // float4[128]: {W1row0, W1row1, W1row2, b1} per k = 2048
#define OFF_PB 71680          // float2[128]: {b2[o], W3[o]} = 1024
#define SMEM_TOTAL 72704      // 71 KB -> 2 CTAs/SM

#define BLOCK 224             // 7 warps: grid 293 ~= 296 resident slots (load balance)

// Pre-converted W2 image (hi/lo fp16, smem layout) written by prep kernel.
__device__ __align__(16) unsigned char g_w2img[W2IMG_BYTES];

// softplus: max(x,0) + log(1 + exp(-|x|))   (proven R11/R13 form)
__device__ __forceinline__ float softplusf(float x) {
    float u = __expf(-fabsf(x));
    return fmaxf(x, 0.0f) + __logf(1.0f + u);
}

__device__ __forceinline__ void ldsm4(uint32_t* r, uint32_t a) {
    asm volatile("ldmatrix.sync.aligned.m8n8.x4.shared.b16 {%0,%1,%2,%3}, [%4];"
        : "=r"(r[0]), "=r"(r[1]), "=r"(r[2]), "=r"(r[3]) : "r"(a));
}
__device__ __forceinline__ void mma16816(float* c, const uint32_t* a, const uint32_t* b) {
    asm volatile("mma.sync.aligned.m16n8k16.row.col.f32.f16.f16.f32 "
        "{%0,%1,%2,%3}, {%4,%5,%6,%7}, {%8,%9}, {%0,%1,%2,%3};"
        : "+f"(c[0]), "+f"(c[1]), "+f"(c[2]), "+f"(c[3])
        : "r"(a[0]), "r"(a[1]), "r"(a[2]), "r"(a[3]), "r"(b[0]), "r"(b[1]));
}

__device__ __forceinline__ uint32_t pack_h2(float lo, float hi) {
    __half2 h = __halves2half2(__float2half_rn(lo), __float2half_rn(hi));
    return *reinterpret_cast<uint32_t*>(&h);
}

// one h value: x -> clamp(softplus(x))
#define H_FROM_X(x, hname) float hname = fminf(softplusf(x), 60000.0f)

// layer-1 B fragments for ONE 8-point group (single/fix path).
__device__ __forceinline__ void layer1_frags(
    float qx, float qy, float qz, int q,
    const float4* __restrict__ PK,
    uint32_t (&bhi)[8][2], uint32_t (&blo)[8][2])
{
#pragma unroll
    for (int kt = 0; kt < 8; kt++) {
        int k0 = kt * 16 + 2 * q;
        float4 A = PK[k0];
        float4 B = PK[k0 + 1];
        float4 C = PK[k0 + 8];
        float4 D = PK[k0 + 9];
        H_FROM_X(fmaf(qx, A.x, fmaf(qy, A.y, fmaf(qz, A.z, A.w))), h00);
        H_FROM_X(fmaf(qx, B.x, fmaf(qy, B.y, fmaf(qz, B.z, B.w))), h01);
        H_FROM_X(fmaf(qx, C.x, fmaf(qy, C.y, fmaf(qz, C.z, C.w))), h08);
        H_FROM_X(fmaf(qx, D.x, fmaf(qy, D.y, fmaf(qz, D.z, D.w))), h09);
        bhi[kt][0] = pack_h2(h00, h01);
        bhi[kt][1] = pack_h2(h08, h09);
        __half t0 = __float2half_rn(h00), t1 = __float2half_rn(h01);
        __half t8 = __float2half_rn(h08), t9 = __float2half_rn(h09);
        blo[kt][0] = pack_h2(h00 - __half2float(t0), h01 - __half2float(t1));
        blo[kt][1] = pack_h2(h08 - __half2float(t8), h09 - __half2float(t9));
    }
}

// FUSED layer-1 for a PAIR of groups: loads each PK float4 once; arithmetic
// bitwise identical to two separate calls.
__device__ __forceinline__ void layer1_pair(
    float q0x, float q0y, float q0z,
    float q1x, float q1y, float q1z, int q,
    const float4* __restrict__ PK,
    uint32_t (&h0)[8][2], uint32_t (&l0)[8][2],
    uint32_t (&h1)[8][2], uint32_t (&l1)[8][2])
{
#pragma unroll
    for (int kt = 0; kt < 8; kt++) {
        int k0 = kt * 16 + 2 * q;
        float4 A = PK[k0];
        float4 B = PK[k0 + 1];
        float4 C = PK[k0 + 8];
        float4 D = PK[k0 + 9];
        H_FROM_X(fmaf(q0x, A.x, fmaf(q0y, A.y, fmaf(q0z, A.z, A.w))), a00);
        H_FROM_X(fmaf(q0x, B.x, fmaf(q0y, B.y, fmaf(q0z, B.z, B.w))), a01);
        H_FROM_X(fmaf(q0x, C.x, fmaf(q0y, C.y, fmaf(q0z, C.z, C.w))), a08);
        H_FROM_X(fmaf(q0x, D.x, fmaf(q0y, D.y, fmaf(q0z, D.z, D.w))), a09);
        H_FROM_X(fmaf(q1x, A.x, fmaf(q1y, A.y, fmaf(q1z, A.z, A.w))), b00);
        H_FROM_X(fmaf(q1x, B.x, fmaf(q1y, B.y, fmaf(q1z, B.z, B.w))), b01);
        H_FROM_X(fmaf(q1x, C.x, fmaf(q1y, C.y, fmaf(q1z, C.z, C.w))), b08);
        H_FROM_X(fmaf(q1x, D.x, fmaf(q1y, D.y, fmaf(q1z, D.z, D.w))), b09);
        h0[kt][0] = pack_h2(a00, a01);
        h0[kt][1] = pack_h2(a08, a09);
        h1[kt][0] = pack_h2(b00, b01);
        h1[kt][1] = pack_h2(b08, b09);
        __half u0 = __float2half_rn(a00), u1 = __float2half_rn(a01);
        __half u8 = __float2half_rn(a08), u9 = __float2half_rn(a09);
        l0[kt][0] = pack_h2(a00 - __half2float(u0), a01 - __half2float(u1));
        l0[kt][1] = pack_h2(a08 - __half2float(u8), a09 - __half2float(u9));
        __half v0 = __float2half_rn(b00), v1 = __float2half_rn(b01);
        __half v8 = __float2half_rn(b08), v9 = __float2half_rn(b09);
        l1[kt][0] = pack_h2(b00 - __half2float(v0), b01 - __half2float(v1));
        l1[kt][1] = pack_h2(b08 - __half2float(v8), b09 - __half2float(v9));
    }
}

// ---------------------------------------------------------------------------
// Warp-collective SDF eval with lane COMPACTION — now fully smem-free and
// sync-free: slot->lane via __fns on the ballot, results routed back with
// one shfl per group (after the g-reduction, every lane with matching q
// holds the point's value). Arithmetic per point is unchanged.
// ---------------------------------------------------------------------------
__device__ __noinline__ float sdf_eval_warp(float px, float py, float pz,
                                            bool need, float b3)
{
    extern __shared__ char dsm[];
    const int tid  = threadIdx.x;
    const int lane = tid & 31;
    const int q    = lane & 3;
    const int g    = lane >> 2;
    const uint32_t smem0 = (uint32_t)__cvta_generic_to_shared(dsm);
    const float4* PK = (const float4*)(dsm + OFF_PK);
    const float2* PB = (const float2*)(dsm + OFF_PB);

    const uint32_t full = 0xFFFFFFFFu;
    const uint32_t bal = __ballot_sync(full, need);
    const int nact = __popc(bal);
    const int myslot = __popc(bal & ((1u << lane) - 1u));
    const int qp = (myslot & 7) >> 1;       // q of the lane-column holding my value
    const int mg = myslot >> 3;             // group index holding my value
    float res = 0.0f;

    const int ngroups = (nact + 7) >> 3;
    const uint32_t lanebase =
        (uint32_t)((((lane >> 3) & 1) * 8 + (lane & 7)) * ROWB + (lane >> 4) * 16);

#pragma unroll 1
    for (int gb = 0; gb < ngroups; gb += 2) {
        const bool paired = (gb + 1) < ngroups;
        const int s0 = 8 * gb + g;
        const int src0 = (s0 < nact) ? (int)__fns(bal, 0, s0 + 1) : 0;
        float q0x = __shfl_sync(full, px, src0);
        float q0y = __shfl_sync(full, py, src0);
        float q0z = __shfl_sync(full, pz, src0);

        if (paired) {
            const int s1 = s0 + 8;
            const int src1 = (s1 < nact) ? (int)__fns(bal, 0, s1 + 1) : 0;
            float q1x = __shfl_sync(full, px, src1);
            float q1y = __shfl_sync(full, py, src1);
            float q1z = __shfl_sync(full, pz, src1);
            uint32_t h0[8][2], l0[8][2], h1[8][2], l1[8][2];
            layer1_pair(q0x, q0y, q0z, q1x, q1y, q1z, q, PK, h0, l0, h1, l1);

            float P0 = 0.f, P1 = 0.f, P2 = 0.f, P3 = 0.f;
#pragma unroll 2
            for (int mt = 0; mt < 8; mt++) {
                int o0 = mt * 16 + g, o1 = o0 + 8;
                float2 pb0 = PB[o0];
                float2 pb1 = PB[o1];
                float c0[4] = {pb0.x, pb0.x, pb1.x, pb1.x};
                float c1[4] = {pb0.x, pb0.x, pb1.x, pb1.x};
                uint32_t abase = smem0 + (uint32_t)(mt * 16 * ROWB) + lanebase;
#pragma unroll
                for (int kt = 0; kt < 8; kt++) {
                    uint32_t ah[4], al[4];
                    ldsm4(ah, abase + SW_HI + kt * 32);
                    ldsm4(al, abase + SW_LO + kt * 32);
                    mma16816(c0, ah, h0[kt]);
                    mma16816(c0, ah, l0[kt]);
                    mma16816(c0, al, h0[kt]);
                    mma16816(c1, ah, h1[kt]);
                    mma16816(c1, ah, l1[kt]);
                    mma16816(c1, al, h1[kt]);
                }
                P0 = fmaf(softplusf(c0[0]), pb0.y, fmaf(softplusf(c0[2]), pb1.y, P0));
                P1 = fmaf(softplusf(c0[1]), pb0.y, fmaf(softplusf(c0[3]), pb1.y, P1));
                P2 = fmaf(softplusf(c1[0]), pb0.y, fmaf(softplusf(c1[2]), pb1.y, P2));
                P3 = fmaf(softplusf(c1[1]), pb0.y, fmaf(softplusf(c1[3]), pb1.y, P3));
            }
            P0 += __shfl_xor_sync(full, P0, 4);
            P0 += __shfl_xor_sync(full, P0, 8);
            P0 += __shfl_xor_sync(full, P0, 16);
            P1 += __shfl_xor_sync(full, P1, 4);
            P1 += __shfl_xor_sync(full, P1, 8);
            P1 += __shfl_xor_sync(full, P1, 16);
            P2 += __shfl_xor_sync(full, P2, 4);
            P2 += __shfl_xor_sync(full, P2, 8);
            P2 += __shfl_xor_sync(full, P2, 16);
            P3 += __shfl_xor_sync(full, P3, 4);
            P3 += __shfl_xor_sync(full, P3, 8);
            P3 += __shfl_xor_sync(full, P3, 16);
            // route results: every lane with q == qp holds my slot's sums
            float g0 = __shfl_sync(full, P0, qp);
            float g1 = __shfl_sync(full, P1, qp);
            float g2 = __shfl_sync(full, P2, qp);
            float g3 = __shfl_sync(full, P3, qp);
            if (mg == gb)          res = (myslot & 1) ? g1 : g0;
            else if (mg == gb + 1) res = (myslot & 1) ? g3 : g2;
        } else {
            uint32_t bh[8][2], bl[8][2];
            layer1_frags(q0x, q0y, q0z, q, PK, bh, bl);

            float P0 = 0.f, P1 = 0.f;
#pragma unroll 2
            for (int mt = 0; mt < 8; mt++) {
                int o0 = mt * 16 + g, o1 = o0 + 8;
                float2 pb0 = PB[o0];
                float2 pb1 = PB[o1];
                float c[4] = {pb0.x, pb0.x, pb1.x, pb1.x};
                uint32_t abase = smem0 + (uint32_t)(mt * 16 * ROWB) + lanebase;
#pragma unroll
                for (int kt = 0; kt < 8; kt++) {
                    uint32_t ah[4], al[4];
                    ldsm4(ah, abase + SW_HI + kt * 32);
                    ldsm4(al, abase + SW_LO + kt * 32);
                    mma16816(c, ah, bh[kt]);
                    mma16816(c, ah, bl[kt]);
                    mma16816(c, al, bh[kt]);
                }
                P0 = fmaf(softplusf(c[0]), pb0.y, fmaf(softplusf(c[2]), pb1.y, P0));
                P1 = fmaf(softplusf(c[1]), pb0.y, fmaf(softplusf(c[3]), pb1.y, P1));
            }
            P0 += __shfl_xor_sync(full, P0, 4);
            P0 += __shfl_xor_sync(full, P0, 8);
            P0 += __shfl_xor_sync(full, P0, 16);
            P1 += __shfl_xor_sync(full, P1, 4);
            P1 += __shfl_xor_sync(full, P1, 8);
            P1 += __shfl_xor_sync(full, P1, 16);
            float g0 = __shfl_sync(full, P0, qp);
            float g1 = __shfl_sync(full, P1, qp);
            if (mg == gb) res = (myslot & 1) ? g1 : g0;
        }
    }
    return b3 + res;   // valid for 'need' lanes; ignored otherwise
}

// ---------------------------------------------------------------------------
// Prep kernel: convert W2 -> hi/lo fp16 smem image once (instead of per-CTA).
// ---------------------------------------------------------------------------
__global__ void prep_kernel(const float* __restrict__ gW2)
{
    int idx = blockIdx.x * blockDim.x + threadIdx.x;
    if (idx < HID * HID) {
        int m = idx & 127, k = idx >> 7;
        float w = gW2[idx];
        __half h = __float2half_rn(w);
        __half l = __float2half_rn(w - __half2float(h));
        *(__half*)(g_w2img + SW_HI + m * ROWB + k * 2) = h;
        *(__half*)(g_w2img + SW_LO + m * ROWB + k * 2) = l;
    }
}

// ---------------------------------------------------------------------------
__global__ void __launch_bounds__(BLOCK, 2)
sphere_trace_kernel(const float* __restrict__ rays_d,
                    const float* __restrict__ rays_o,
                    const float* __restrict__ gW1,
                    const float* __restrict__ gb1,
                    const float* __restrict__ gb2,
                    const float* __restrict__ gW3,
                    const float* __restrict__ gb3,
                    float* __restrict__ out,
                    int n)
{
    extern __shared__ char dsm[];
    const int tid = threadIdx.x;

    // stage pre-converted W2 image with vector copies (coalesced, no converts)
    {
        const uint4* src = (const uint4*)g_w2img;
        uint4* dst = (uint4*)dsm;
        for (int i = tid; i < W2IMG_BYTES / 16; i += blockDim.x)
            dst[i] = src[i];
    }
    {
        float4* PK = (float4*)(dsm + OFF_PK);
        float2* PB = (float2*)(dsm + OFF_PB);
        for (int k = tid; k < HID; k += blockDim.x) {
            PK[k] = make_float4(gW1[k], gW1[128 + k], gW1[256 + k], gb1[k]);
            PB[k] = make_float2(gb2[k], gW3[k]);
        }
    }
    float b3 = gb3[0];
    __syncthreads();

    const int total = 2 * n;
    int t = blockIdx.x * blockDim.x + tid;
    const bool valid = (t < total);
    int tc  = valid ? t : (total - 1);
    int ray = tc >> 1;
    int ch  = tc & 1;
    float sgn = ch ? -1.0f : 1.0f;

    float dx = rays_d[ray * 3 + 0];
    float dy = rays_d[ray * 3 + 1];
    float dz = rays_d[ray * 3 + 2];
    float ox = rays_o[ray * 3 + 0];
    float oy = rays_o[ray * 3 + 1];
    float oz = rays_o[ray * 3 + 2];

    const uint32_t full = 0xFFFFFFFFu;

    // Initial eval at z=0: both channels of a ray share the SAME origin point,
    // so only even (ch==0) lanes evaluate; odd lanes take the partner's value.
    float z = 0.0f;
    float s0 = sdf_eval_warp(ox, oy, oz, valid && (ch == 0), b3);
    float s0p = __shfl_xor_sync(full, s0, 1);
    float next_sdf = (ch == 0) ? s0 : s0p;
    next_sdf = valid ? next_sdf : 0.0f;     // kill tail lanes immediately
    bool mask = valid;

#pragma unroll 1
    for (int it = 0; it < 6; it++) {
        float sdf_vals = mask ? next_sdf : 0.0f;
        if (sdf_vals <= SDF_THRESH) sdf_vals = 0.0f;
        mask = mask && (sdf_vals > SDF_THRESH);
        z = fmaf(sgn, sdf_vals, z);

        if (__any_sync(full, mask)) {
            float s = sdf_eval_warp(fmaf(z, dx, ox), fmaf(z, dy, oy),
                                    fmaf(z, dz, oz), mask, b3);
            next_sdf = mask ? s : 0.0f;
        } else {
            next_sdf = 0.0f;
        }

        bool fmask = next_sdf < 0.0f;
#pragma unroll 1
        for (int i = 0; i < 3; i++) {
            float step = 0.5f / (float)(1 << i);   // 0.5, 0.25, 0.125 exact
            if (__any_sync(full, fmask)) {
                float zc = fmask ? (z - step * sgn * sdf_vals) : z;
                float s2 = sdf_eval_warp(fmaf(zc, dx, ox), fmaf(zc, dy, oy),
                                         fmaf(zc, dz, oz), fmask, b3);
                z = zc;
                if (fmask) next_sdf = s2;
            }
            fmask = next_sdf < 0.0f;
        }

        // mask &= (z_ch0 < z_ch1): channels are adjacent lanes
        float zo = __shfl_xor_sync(full, z, 1);
        bool cond = (ch == 0) ? (z < zo) : (zo < z);
        mask = mask && cond;
    }

    {   // final top-of-loop mask update
        float sdf_vals = mask ? next_sdf : 0.0f;
        if (sdf_vals <= SDF_THRESH) sdf_vals = 0.0f;
        mask = mask && (sdf_vals > SDF_THRESH);
    }

    if (valid) {
        float px = fmaf(z, dx, ox);
        float py = fmaf(z, dy, oy);
        float pz = fmaf(z, dz, oz);
        long basei = (long)ch * n + ray;
        // output layout: points (2,n,3) | z_vals (2,n) | mask (2,n)
        out[basei * 3 + 0] = px;
        out[basei * 3 + 1] = py;
        out[basei * 3 + 2] = pz;
        out[(long)6 * n + basei] = z;
        out[(long)8 * n + basei] = mask ? 1.0f : 0.0f;
    }
}

extern "C" void kernel_launch(void* const* d_in, const int* in_sizes, int n_in,
                              void* d_out, int out_size)
{
    const float* rays_d = (const float*)d_in[0];
    const float* rays_o = (const float*)d_in[1];
    const float* W1     = (const float*)d_in[2];
    const float* b1     = (const float*)d_in[3];
    const float* W2     = (const float*)d_in[4];
    const float* b2     = (const float*)d_in[5];
    const float* W3     = (const float*)d_in[6];
    const float* b3     = (const float*)d_in[7];

    int n = in_sizes[0] / 3;        // N_RAYS
    int total = 2 * n;
    int block = BLOCK;
    int grid = (total + block - 1) / block;

    // 1) convert W2 once into the gmem image
    prep_kernel<<<(HID * HID + 255) / 256, 256>>>(W2);

    // 2) main trace (stages the image with uint4 copies)
    cudaFuncSetAttribute(sphere_trace_kernel,
                         cudaFuncAttributeMaxDynamicSharedMemorySize,
                         SMEM_TOTAL);
    sphere_trace_kernel<<<grid, block, SMEM_TOTAL>>>(
        rays_d, rays_o, W1, b1, b2, W3, b3, (float*)d_out, n);
}

// round 17
// speedup vs baseline: 1.1570x; 1.1570x over previous
#include <cuda_runtime.h>
#include <cuda_fp16.h>
#include <cstdint>
#include <math.h>

#define HID 128
#define SDF_THRESH 5e-05f
#define ROWB 272              // padded row stride (bytes) for fp16[128] rows

// shared-memory byte offsets (per-CTA dynamic, all 16B aligned)
#define SW_HI  0              // W2' hi: 128 rows x 272B = 34816  (W2'[m][k] = W2[k][m])
#define W2IMG_BYTES 34816     // hi image only (Al*Bh product dropped)
#define OFF_PK 34816          // float4[128]: {W1row0, W1row1, W1row2, b1} per k = 2048
#define OFF_PB 36864          // float2[128]: {b2[o], W3[o]} = 1024
#define SMEM_TOTAL 37888      // 37 KB -> 2 CTAs/SM (reg-capped)

#define BLOCK 224             // 7 warps: grid 293 ~= 296 resident slots (load balance)

// Pre-converted W2-hi image (fp16, smem layout) written by prep kernel.
__device__ __align__(16) unsigned char g_w2img[W2IMG_BYTES];

// softplus: max(x,0) + log(1 + exp(-|x|))   (proven R11/R13 form)
__device__ __forceinline__ float softplusf(float x) {
    float u = __expf(-fabsf(x));
    return fmaxf(x, 0.0f) + __logf(1.0f + u);
}

__device__ __forceinline__ void ldsm4(uint32_t* r, uint32_t a) {
    asm volatile("ldmatrix.sync.aligned.m8n8.x4.shared.b16 {%0,%1,%2,%3}, [%4];"
        : "=r"(r[0]), "=r"(r[1]), "=r"(r[2]), "=r"(r[3]) : "r"(a));
}
__device__ __forceinline__ void mma16816(float* c, const uint32_t* a, const uint32_t* b) {
    asm volatile("mma.sync.aligned.m16n8k16.row.col.f32.f16.f16.f32 "
        "{%0,%1,%2,%3}, {%4,%5,%6,%7}, {%8,%9}, {%0,%1,%2,%3};"
        : "+f"(c[0]), "+f"(c[1]), "+f"(c[2]), "+f"(c[3])
        : "r"(a[0]), "r"(a[1]), "r"(a[2]), "r"(a[3]), "r"(b[0]), "r"(b[1]));
}

__device__ __forceinline__ uint32_t pack_h2(float lo, float hi) {
    __half2 h = __halves2half2(__float2half_rn(lo), __float2half_rn(hi));
    return *reinterpret_cast<uint32_t*>(&h);
}

// one h value: x -> clamp(softplus(x))
#define H_FROM_X(x, hname) float hname = fminf(softplusf(x), 60000.0f)

// layer-1 B fragments for ONE 8-point group (single/fix path).
// h hi fp16 + fp32->fp16 residual (residual still corrected via Ah*Bl).
__device__ __forceinline__ void layer1_frags(
    float qx, float qy, float qz, int q,
    const float4* __restrict__ PK,
    uint32_t (&bhi)[8][2], uint32_t (&blo)[8][2])
{
#pragma unroll
    for (int kt = 0; kt < 8; kt++) {
        int k0 = kt * 16 + 2 * q;
        float4 A = PK[k0];
        float4 B = PK[k0 + 1];
        float4 C = PK[k0 + 8];
        float4 D = PK[k0 + 9];
        H_FROM_X(fmaf(qx, A.x, fmaf(qy, A.y, fmaf(qz, A.z, A.w))), h00);
        H_FROM_X(fmaf(qx, B.x, fmaf(qy, B.y, fmaf(qz, B.z, B.w))), h01);
        H_FROM_X(fmaf(qx, C.x, fmaf(qy, C.y, fmaf(qz, C.z, C.w))), h08);
        H_FROM_X(fmaf(qx, D.x, fmaf(qy, D.y, fmaf(qz, D.z, D.w))), h09);
        bhi[kt][0] = pack_h2(h00, h01);
        bhi[kt][1] = pack_h2(h08, h09);
        __half t0 = __float2half_rn(h00), t1 = __float2half_rn(h01);
        __half t8 = __float2half_rn(h08), t9 = __float2half_rn(h09);
        blo[kt][0] = pack_h2(h00 - __half2float(t0), h01 - __half2float(t1));
        blo[kt][1] = pack_h2(h08 - __half2float(t8), h09 - __half2float(t9));
    }
}

// FUSED layer-1 for a PAIR of groups: loads each PK float4 once.
__device__ __forceinline__ void layer1_pair(
    float q0x, float q0y, float q0z,
    float q1x, float q1y, float q1z, int q,
    const float4* __restrict__ PK,
    uint32_t (&h0)[8][2], uint32_t (&l0)[8][2],
    uint32_t (&h1)[8][2], uint32_t (&l1)[8][2])
{
#pragma unroll
    for (int kt = 0; kt < 8; kt++) {
        int k0 = kt * 16 + 2 * q;
        float4 A = PK[k0];
        float4 B = PK[k0 + 1];
        float4 C = PK[k0 + 8];
        float4 D = PK[k0 + 9];
        H_FROM_X(fmaf(q0x, A.x, fmaf(q0y, A.y, fmaf(q0z, A.z, A.w))), a00);
        H_FROM_X(fmaf(q0x, B.x, fmaf(q0y, B.y, fmaf(q0z, B.z, B.w))), a01);
        H_FROM_X(fmaf(q0x, C.x, fmaf(q0y, C.y, fmaf(q0z, C.z, C.w))), a08);
        H_FROM_X(fmaf(q0x, D.x, fmaf(q0y, D.y, fmaf(q0z, D.z, D.w))), a09);
        H_FROM_X(fmaf(q1x, A.x, fmaf(q1y, A.y, fmaf(q1z, A.z, A.w))), b00);
        H_FROM_X(fmaf(q1x, B.x, fmaf(q1y, B.y, fmaf(q1z, B.z, B.w))), b01);
        H_FROM_X(fmaf(q1x, C.x, fmaf(q1y, C.y, fmaf(q1z, C.z, C.w))), b08);
        H_FROM_X(fmaf(q1x, D.x, fmaf(q1y, D.y, fmaf(q1z, D.z, D.w))), b09);
        h0[kt][0] = pack_h2(a00, a01);
        h0[kt][1] = pack_h2(a08, a09);
        h1[kt][0] = pack_h2(b00, b01);
        h1[kt][1] = pack_h2(b08, b09);
        __half u0 = __float2half_rn(a00), u1 = __float2half_rn(a01);
        __half u8 = __float2half_rn(a08), u9 = __float2half_rn(a09);
        l0[kt][0] = pack_h2(a00 - __half2float(u0), a01 - __half2float(u1));
        l0[kt][1] = pack_h2(a08 - __half2float(u8), a09 - __half2float(u9));
        __half v0 = __float2half_rn(b00), v1 = __float2half_rn(b01);
        __half v8 = __float2half_rn(b08), v9 = __float2half_rn(b09);
        l1[kt][0] = pack_h2(b00 - __half2float(v0), b01 - __half2float(v1));
        l1[kt][1] = pack_h2(b08 - __half2float(v8), b09 - __half2float(v9));
    }
}

// ---------------------------------------------------------------------------
// Warp-collective SDF eval, smem-free scaffold (__fns compaction + shfl
// routing). 2 MMA products per accumulation: Ah*Bh + Ah*Bl (Al*Bh dropped;
// W2 fp16-residual error ~1e-4 rel, 10x under tolerance).
// ---------------------------------------------------------------------------
__device__ __noinline__ float sdf_eval_warp(float px, float py, float pz,
                                            bool need, float b3)
{
    extern __shared__ char dsm[];
    const int tid  = threadIdx.x;
    const int lane = tid & 31;
    const int q    = lane & 3;
    const int g    = lane >> 2;
    const uint32_t smem0 = (uint32_t)__cvta_generic_to_shared(dsm);
    const float4* PK = (const float4*)(dsm + OFF_PK);
    const float2* PB = (const float2*)(dsm + OFF_PB);

    const uint32_t full = 0xFFFFFFFFu;
    const uint32_t bal = __ballot_sync(full, need);
    const int nact = __popc(bal);
    const int myslot = __popc(bal & ((1u << lane) - 1u));
    const int qp = (myslot & 7) >> 1;       // q of the lane-column holding my value
    const int mg = myslot >> 3;             // group index holding my value
    float res = 0.0f;

    const int ngroups = (nact + 7) >> 3;
    const uint32_t lanebase =
        (uint32_t)((((lane >> 3) & 1) * 8 + (lane & 7)) * ROWB + (lane >> 4) * 16);

#pragma unroll 1
    for (int gb = 0; gb < ngroups; gb += 2) {
        const bool paired = (gb + 1) < ngroups;
        const int s0 = 8 * gb + g;
        const int src0 = (s0 < nact) ? (int)__fns(bal, 0, s0 + 1) : 0;
        float q0x = __shfl_sync(full, px, src0);
        float q0y = __shfl_sync(full, py, src0);
        float q0z = __shfl_sync(full, pz, src0);

        if (paired) {
            const int s1 = s0 + 8;
            const int src1 = (s1 < nact) ? (int)__fns(bal, 0, s1 + 1) : 0;
            float q1x = __shfl_sync(full, px, src1);
            float q1y = __shfl_sync(full, py, src1);
            float q1z = __shfl_sync(full, pz, src1);
            uint32_t h0[8][2], l0[8][2], h1[8][2], l1[8][2];
            layer1_pair(q0x, q0y, q0z, q1x, q1y, q1z, q, PK, h0, l0, h1, l1);

            float P0 = 0.f, P1 = 0.f, P2 = 0.f, P3 = 0.f;
#pragma unroll 2
            for (int mt = 0; mt < 8; mt++) {
                int o0 = mt * 16 + g, o1 = o0 + 8;
                float2 pb0 = PB[o0];
                float2 pb1 = PB[o1];
                float c0[4] = {pb0.x, pb0.x, pb1.x, pb1.x};
                float c1[4] = {pb0.x, pb0.x, pb1.x, pb1.x};
                uint32_t abase = smem0 + (uint32_t)(mt * 16 * ROWB) + lanebase;
#pragma unroll
                for (int kt = 0; kt < 8; kt++) {
                    uint32_t ah[4];
                    ldsm4(ah, abase + SW_HI + kt * 32);
                    mma16816(c0, ah, h0[kt]);
                    mma16816(c0, ah, l0[kt]);
                    mma16816(c1, ah, h1[kt]);
                    mma16816(c1, ah, l1[kt]);
                }
                P0 = fmaf(softplusf(c0[0]), pb0.y, fmaf(softplusf(c0[2]), pb1.y, P0));
                P1 = fmaf(softplusf(c0[1]), pb0.y, fmaf(softplusf(c0[3]), pb1.y, P1));
                P2 = fmaf(softplusf(c1[0]), pb0.y, fmaf(softplusf(c1[2]), pb1.y, P2));
                P3 = fmaf(softplusf(c1[1]), pb0.y, fmaf(softplusf(c1[3]), pb1.y, P3));
            }
            P0 += __shfl_xor_sync(full, P0, 4);
            P0 += __shfl_xor_sync(full, P0, 8);
            P0 += __shfl_xor_sync(full, P0, 16);
            P1 += __shfl_xor_sync(full, P1, 4);
            P1 += __shfl_xor_sync(full, P1, 8);
            P1 += __shfl_xor_sync(full, P1, 16);
            P2 += __shfl_xor_sync(full, P2, 4);
            P2 += __shfl_xor_sync(full, P2, 8);
            P2 += __shfl_xor_sync(full, P2, 16);
            P3 += __shfl_xor_sync(full, P3, 4);
            P3 += __shfl_xor_sync(full, P3, 8);
            P3 += __shfl_xor_sync(full, P3, 16);
            float g0 = __shfl_sync(full, P0, qp);
            float g1 = __shfl_sync(full, P1, qp);
            float g2 = __shfl_sync(full, P2, qp);
            float g3 = __shfl_sync(full, P3, qp);
            if (mg == gb)          res = (myslot & 1) ? g1 : g0;
            else if (mg == gb + 1) res = (myslot & 1) ? g3 : g2;
        } else {
            uint32_t bh[8][2], bl[8][2];
            layer1_frags(q0x, q0y, q0z, q, PK, bh, bl);

            float P0 = 0.f, P1 = 0.f;
#pragma unroll 2
            for (int mt = 0; mt < 8; mt++) {
                int o0 = mt * 16 + g, o1 = o0 + 8;
                float2 pb0 = PB[o0];
                float2 pb1 = PB[o1];
                float c[4] = {pb0.x, pb0.x, pb1.x, pb1.x};
                uint32_t abase = smem0 + (uint32_t)(mt * 16 * ROWB) + lanebase;
#pragma unroll
                for (int kt = 0; kt < 8; kt++) {
                    uint32_t ah[4];
                    ldsm4(ah, abase + SW_HI + kt * 32);
                    mma16816(c, ah, bh[kt]);
                    mma16816(c, ah, bl[kt]);
                }
                P0 = fmaf(softplusf(c[0]), pb0.y, fmaf(softplusf(c[2]), pb1.y, P0));
                P1 = fmaf(softplusf(c[1]), pb0.y, fmaf(softplusf(c[3]), pb1.y, P1));
            }
            P0 += __shfl_xor_sync(full, P0, 4);
            P0 += __shfl_xor_sync(full, P0, 8);
            P0 += __shfl_xor_sync(full, P0, 16);
            P1 += __shfl_xor_sync(full, P1, 4);
            P1 += __shfl_xor_sync(full, P1, 8);
            P1 += __shfl_xor_sync(full, P1, 16);
            float g0 = __shfl_sync(full, P0, qp);
            float g1 = __shfl_sync(full, P1, qp);
            if (mg == gb) res = (myslot & 1) ? g1 : g0;
        }
    }
    return b3 + res;   // valid for 'need' lanes; ignored otherwise
}

// ---------------------------------------------------------------------------
// Prep kernel: convert W2 -> hi fp16 smem image once.
// ---------------------------------------------------------------------------
__global__ void prep_kernel(const float* __restrict__ gW2)
{
    int idx = blockIdx.x * blockDim.x + threadIdx.x;
    if (idx < HID * HID) {
        int m = idx & 127, k = idx >> 7;
        *(__half*)(g_w2img + SW_HI + m * ROWB + k * 2) = __float2half_rn(gW2[idx]);
    }
}

// ---------------------------------------------------------------------------
__global__ void __launch_bounds__(BLOCK, 2)
sphere_trace_kernel(const float* __restrict__ rays_d,
                    const float* __restrict__ rays_o,
                    const float* __restrict__ gW1,
                    const float* __restrict__ gb1,
                    const float* __restrict__ gb2,
                    const float* __restrict__ gW3,
                    const float* __restrict__ gb3,
                    float* __restrict__ out,
                    int n)
{
    extern __shared__ char dsm[];
    const int tid = threadIdx.x;

    // stage pre-converted W2-hi image with vector copies
    {
        const uint4* src = (const uint4*)g_w2img;
        uint4* dst = (uint4*)dsm;
        for (int i = tid; i < W2IMG_BYTES / 16; i += blockDim.x)
            dst[i] = src[i];
    }
    {
        float4* PK = (float4*)(dsm + OFF_PK);
        float2* PB = (float2*)(dsm + OFF_PB);
        for (int k = tid; k < HID; k += blockDim.x) {
            PK[k] = make_float4(gW1[k], gW1[128 + k], gW1[256 + k], gb1[k]);
            PB[k] = make_float2(gb2[k], gW3[k]);
        }
    }
    float b3 = gb3[0];
    __syncthreads();

    const int total = 2 * n;
    int t = blockIdx.x * blockDim.x + tid;
    const bool valid = (t < total);
    int tc  = valid ? t : (total - 1);
    int ray = tc >> 1;
    int ch  = tc & 1;
    float sgn = ch ? -1.0f : 1.0f;

    float dx = rays_d[ray * 3 + 0];
    float dy = rays_d[ray * 3 + 1];
    float dz = rays_d[ray * 3 + 2];
    float ox = rays_o[ray * 3 + 0];
    float oy = rays_o[ray * 3 + 1];
    float oz = rays_o[ray * 3 + 2];

    const uint32_t full = 0xFFFFFFFFu;

    // Initial eval at z=0: both channels share the SAME origin point.
    float z = 0.0f;
    float s0 = sdf_eval_warp(ox, oy, oz, valid && (ch == 0), b3);
    float s0p = __shfl_xor_sync(full, s0, 1);
    float next_sdf = (ch == 0) ? s0 : s0p;
    next_sdf = valid ? next_sdf : 0.0f;     // kill tail lanes immediately
    bool mask = valid;

#pragma unroll 1
    for (int it = 0; it < 6; it++) {
        float sdf_vals = mask ? next_sdf : 0.0f;
        if (sdf_vals <= SDF_THRESH) sdf_vals = 0.0f;
        mask = mask && (sdf_vals > SDF_THRESH);
        z = fmaf(sgn, sdf_vals, z);

        if (__any_sync(full, mask)) {
            float s = sdf_eval_warp(fmaf(z, dx, ox), fmaf(z, dy, oy),
                                    fmaf(z, dz, oz), mask, b3);
            next_sdf = mask ? s : 0.0f;
        } else {
            next_sdf = 0.0f;
        }

        bool fmask = next_sdf < 0.0f;
#pragma unroll 1
        for (int i = 0; i < 3; i++) {
            float step = 0.5f / (float)(1 << i);   // 0.5, 0.25, 0.125 exact
            if (__any_sync(full, fmask)) {
                float zc = fmask ? (z - step * sgn * sdf_vals) : z;
                float s2 = sdf_eval_warp(fmaf(zc, dx, ox), fmaf(zc, dy, oy),
                                         fmaf(zc, dz, oz), fmask, b3);
                z = zc;
                if (fmask) next_sdf = s2;
            }
            fmask = next_sdf < 0.0f;
        }

        // mask &= (z_ch0 < z_ch1): channels are adjacent lanes
        float zo = __shfl_xor_sync(full, z, 1);
        bool cond = (ch == 0) ? (z < zo) : (zo < z);
        mask = mask && cond;
    }

    {   // final top-of-loop mask update
        float sdf_vals = mask ? next_sdf : 0.0f;
        if (sdf_vals <= SDF_THRESH) sdf_vals = 0.0f;
        mask = mask && (sdf_vals > SDF_THRESH);
    }

    if (valid) {
        float px = fmaf(z, dx, ox);
        float py = fmaf(z, dy, oy);
        float pz = fmaf(z, dz, oz);
        long basei = (long)ch * n + ray;
        // output layout: points (2,n,3) | z_vals (2,n) | mask (2,n)
        out[basei * 3 + 0] = px;
        out[basei * 3 + 1] = py;
        out[basei * 3 + 2] = pz;
        out[(long)6 * n + basei] = z;
        out[(long)8 * n + basei] = mask ? 1.0f : 0.0f;
    }
}

extern "C" void kernel_launch(void* const* d_in, const int* in_sizes, int n_in,
                              void* d_out, int out_size)
{
    const float* rays_d = (const float*)d_in[0];
    const float* rays_o = (const float*)d_in[1];
    const float* W1     = (const float*)d_in[2];
    const float* b1     = (const float*)d_in[3];
    const float* W2     = (const float*)d_in[4];
    const float* b2     = (const float*)d_in[5];
    const float* W3     = (const float*)d_in[6];
    const float* b3     = (const float*)d_in[7];

    int n = in_sizes[0] / 3;        // N_RAYS
    int total = 2 * n;
    int block = BLOCK;
    int grid = (total + block - 1) / block;

    // 1) convert W2 once into the gmem image
    prep_kernel<<<(HID * HID + 255) / 256, 256>>>(W2);

    // 2) main trace
    cudaFuncSetAttribute(sphere_trace_kernel,
                         cudaFuncAttributeMaxDynamicSharedMemorySize,
                         SMEM_TOTAL);
    sphere_trace_kernel<<<grid, block, SMEM_TOTAL>>>(
        rays_d, rays_o, W1, b1, b2, W3, b3, (float*)d_out, n);
}